// round 3
// baseline (speedup 1.0000x reference)
#include <cuda_runtime.h>

#define BATCH 16
#define ECH 32
#define NCLS 3
#define HW 262144           // 512*512
#define HW2 131072
#define TILE_PX 512
#define NTILES 512          // HW / TILE_PX
#define GX 9                // persistent: grid (9,16) = 144 blocks ~= 1 wave
#define NBLK (GX*BATCH)     // 144
#define ROWS 516            // stride mod 32 == 4 -> conflict-free LDS.128 in phase B

// shared memory layout (floats) — double-buffered
#define VALS0 0
#define VALS1 (ECH*ROWS)                 // 16512
#define META0 (2*ECH*ROWS)               // 33024
#define META1 (META0 + TILE_PX)          // 33536
#define OFF_RED (META1 + TILE_PX)        // 34048
#define OFF_SCR (OFF_RED + 8*4*32)       // 35072
#define SM_FLOATS (OFF_SCR + 32)         // 35104
#define SMEM_BYTES (SM_FLOATS*4)         // 140416

// per-block partial results (unique slots -> no zeroing, no atomics on data)
__device__ float g_part[BATCH][GX][4][ECH]; // [0]=sum_emb_l1 [1]=sum_hat_l1 [2]=sum_emb_l2 [3]=sum_hat_l2
__device__ float g_misc[BATCH][GX][3];      // ce, c1, c2
__device__ unsigned int g_sync;             // zero-init; atomicInc wraps -> self-resetting per launch

__global__ __launch_bounds__(256, 1)
void main_kernel(const float* __restrict__ emb,
                 const float* __restrict__ pred,
                 const int*  __restrict__ lab,
                 const int*  __restrict__ nb,
                 float* __restrict__ out) {
    extern __shared__ float sm[];

    const int b    = blockIdx.y;
    const int tid  = threadIdx.x;
    const int wid  = tid >> 5;
    const int lane = tid & 31;

    const float2* emb2 = (const float2*)emb + (size_t)b * ECH  * HW2;
    const float2* pr2  = (const float2*)pred + (size_t)b * NCLS * HW2;
    const int2*   lb2  = (const int2*)lab + (size_t)b * HW2;

    // accumulators (lane == channel in phase B)
    float a1 = 0.f, h1 = 0.f, a2 = 0.f, h2 = 0.f;
    float ce = 0.f;
    int   c1 = 0, c2 = 0;

    // prefetch registers
    float2 v[ECH];
    int2   lp;
    float2 q0, q1, q2;

    // ---------------- prologue: load tile blockIdx.x, consume into buf0 ----------------
    {
        const int qp = blockIdx.x * (TILE_PX / 2) + tid;
        #pragma unroll
        for (int e = 0; e < ECH; e++) v[e] = emb2[e * HW2 + qp];
        lp = lb2[qp];
        q0 = pr2[qp]; q1 = pr2[HW2 + qp]; q2 = pr2[2 * HW2 + qp];

        float* vals  = sm + VALS0;
        float* metaT = sm + META0;
        float sx = 0.f, sy = 0.f;
        #pragma unroll
        for (int e = 0; e < ECH; e++) {
            float2 w = v[e];
            sx = fmaf(w.x, w.x, sx);
            sy = fmaf(w.y, w.y, sy);
            *(float2*)&vals[e * ROWS + 2 * tid] = w;
        }
        float rx = 1.f / fmaxf(sqrtf(sx), 1e-8f);
        float ry = 1.f / fmaxf(sqrtf(sy), 1e-8f);
        metaT[2 * tid]     = (lp.x == 1) ? rx : ((lp.x == 2) ? -rx : 0.f);
        metaT[2 * tid + 1] = (lp.y == 1) ? ry : ((lp.y == 2) ? -ry : 0.f);
        c1 += (lp.x == 1) + (lp.y == 1);
        c2 += (lp.x == 2) + (lp.y == 2);
        float m   = fmaxf(q0.x, fmaxf(q1.x, q2.x));
        ce += m + __logf(__expf(q0.x - m) + __expf(q1.x - m) + __expf(q2.x - m))
              - ((lp.x == 0) ? q0.x : ((lp.x == 1) ? q1.x : q2.x));
        m = fmaxf(q0.y, fmaxf(q1.y, q2.y));
        ce += m + __logf(__expf(q0.y - m) + __expf(q1.y - m) + __expf(q2.y - m))
              - ((lp.y == 0) ? q0.y : ((lp.y == 1) ? q1.y : q2.y));
    }
    __syncthreads();

    // ---------------- pipelined main loop: 1 barrier per tile ----------------
    for (int i = 0; ; i++) {
        const int tn = blockIdx.x + (i + 1) * GX;
        const bool more = (tn < NTILES);

        // issue next tile's global loads (in flight during phase B below)
        if (more) {
            const int qp = tn * (TILE_PX / 2) + tid;
            #pragma unroll
            for (int e = 0; e < ECH; e++) v[e] = emb2[e * HW2 + qp];
            lp = lb2[qp];
            q0 = pr2[qp]; q1 = pr2[HW2 + qp]; q2 = pr2[2 * HW2 + qp];
        }

        // phase B on buffer i&1: warp = 32 channels, 64 px/warp, float4 loads
        {
            const float* vals  = sm + ((i & 1) ? VALS1 : VALS0);
            const float* metaT = sm + ((i & 1) ? META1 : META0);
            const float* vrow = vals  + lane * ROWS + wid * 64;
            const float* mrow = metaT + wid * 64;
            #pragma unroll 4
            for (int k = 0; k < 16; k++) {
                float4 w = *(const float4*)(vrow + 4 * k);
                float4 t = *(const float4*)(mrow + 4 * k);   // broadcast within warp
                float vh0 = w.x * fabsf(t.x);
                float vh1 = w.y * fabsf(t.y);
                float vh2 = w.z * fabsf(t.z);
                float vh3 = w.w * fabsf(t.w);
                if      (t.x > 0.f) { a1 += w.x; h1 += vh0; }
                else if (t.x < 0.f) { a2 += w.x; h2 += vh0; }
                if      (t.y > 0.f) { a1 += w.y; h1 += vh1; }
                else if (t.y < 0.f) { a2 += w.y; h2 += vh1; }
                if      (t.z > 0.f) { a1 += w.z; h1 += vh2; }
                else if (t.z < 0.f) { a2 += w.z; h2 += vh2; }
                if      (t.w > 0.f) { a1 += w.w; h1 += vh3; }
                else if (t.w < 0.f) { a2 += w.w; h2 += vh3; }
            }
        }
        if (!more) break;

        // consume prefetched regs into the other buffer
        {
            float* vals  = sm + (((i + 1) & 1) ? VALS1 : VALS0);
            float* metaT = sm + (((i + 1) & 1) ? META1 : META0);
            float sx = 0.f, sy = 0.f;
            #pragma unroll
            for (int e = 0; e < ECH; e++) {
                float2 w = v[e];
                sx = fmaf(w.x, w.x, sx);
                sy = fmaf(w.y, w.y, sy);
                *(float2*)&vals[e * ROWS + 2 * tid] = w;
            }
            float rx = 1.f / fmaxf(sqrtf(sx), 1e-8f);
            float ry = 1.f / fmaxf(sqrtf(sy), 1e-8f);
            metaT[2 * tid]     = (lp.x == 1) ? rx : ((lp.x == 2) ? -rx : 0.f);
            metaT[2 * tid + 1] = (lp.y == 1) ? ry : ((lp.y == 2) ? -ry : 0.f);
            c1 += (lp.x == 1) + (lp.y == 1);
            c2 += (lp.x == 2) + (lp.y == 2);
            float m   = fmaxf(q0.x, fmaxf(q1.x, q2.x));
            ce += m + __logf(__expf(q0.x - m) + __expf(q1.x - m) + __expf(q2.x - m))
                  - ((lp.x == 0) ? q0.x : ((lp.x == 1) ? q1.x : q2.x));
            m = fmaxf(q0.y, fmaxf(q1.y, q2.y));
            ce += m + __logf(__expf(q0.y - m) + __expf(q1.y - m) + __expf(q2.y - m))
                  - ((lp.y == 0) ? q0.y : ((lp.y == 1) ? q1.y : q2.y));
        }
        __syncthreads();
    }

    // ---------------- block reduction -> unique global slots ----------------
    float* red = sm + OFF_RED;
    float* scr = sm + OFF_SCR;
    __syncthreads();   // protect red/scr region reuse vs last phase B reads
    red[(wid * 4 + 0) * 32 + lane] = a1;
    red[(wid * 4 + 1) * 32 + lane] = h1;
    red[(wid * 4 + 2) * 32 + lane] = a2;
    red[(wid * 4 + 3) * 32 + lane] = h2;
    float cef = ce; float c1f = (float)c1, c2f = (float)c2;
    #pragma unroll
    for (int o = 16; o; o >>= 1) {
        cef += __shfl_xor_sync(0xffffffffu, cef, o);
        c1f += __shfl_xor_sync(0xffffffffu, c1f, o);
        c2f += __shfl_xor_sync(0xffffffffu, c2f, o);
    }
    if (lane == 0) { scr[wid] = cef; scr[8 + wid] = c1f; scr[16 + wid] = c2f; }
    __syncthreads();

    if (wid < 4) {
        float s = 0.f;
        #pragma unroll
        for (int w = 0; w < 8; w++) s += red[(w * 4 + wid) * 32 + lane];
        g_part[b][blockIdx.x][wid][lane] = s;
    }
    if (tid == 0) {
        float tce = 0.f, t1 = 0.f, t2 = 0.f;
        for (int w = 0; w < 8; w++) { tce += scr[w]; t1 += scr[8 + w]; t2 += scr[16 + w]; }
        g_misc[b][blockIdx.x][0] = tce;
        g_misc[b][blockIdx.x][1] = t1;
        g_misc[b][blockIdx.x][2] = t2;
    }

    // ---------------- last-CTA fused finalize ----------------
    __threadfence();
    __syncthreads();
    __shared__ unsigned int s_last;
    if (tid == 0) s_last = atomicInc(&g_sync, NBLK - 1);  // wraps to 0 -> graph-replay safe
    __syncthreads();
    if (s_last != NBLK - 1) return;
    __threadfence();

    // this block reduces all partials; warp w handles images w, w+8 (lane = channel)
    float* part = scr;   // reuse 32-float scratch (only need 16)
    for (int img = wid; img < BATCH; img += 8) {
        float s1 = 0.f, hh1 = 0.f, s2 = 0.f, hh2 = 0.f;
        float ceb = 0.f, cc1 = 0.f, cc2 = 0.f;
        #pragma unroll
        for (int x = 0; x < GX; x++) {
            s1  += g_part[img][x][0][lane];
            hh1 += g_part[img][x][1][lane];
            s2  += g_part[img][x][2][lane];
            hh2 += g_part[img][x][3][lane];
            ceb += g_misc[img][x][0];
            cc1 += g_misc[img][x][1];
            cc2 += g_misc[img][x][2];
        }
        float m1 = s1 / cc1, m2 = s2 / cc2;
        float A  = m1 * m1;
        float Bv = m2 * m2;
        float C  = m1 * m2;
        float D1 = m1 * hh1;
        float D2 = m2 * hh2;
        #pragma unroll
        for (int o = 16; o; o >>= 1) {
            A  += __shfl_xor_sync(0xffffffffu, A,  o);
            Bv += __shfl_xor_sync(0xffffffffu, Bv, o);
            C  += __shfl_xor_sync(0xffffffffu, C,  o);
            D1 += __shfl_xor_sync(0xffffffffu, D1, o);
            D2 += __shfl_xor_sync(0xffffffffu, D2, o);
        }
        if (lane == 0) {
            float n1 = fmaxf(sqrtf(A),  1e-12f);
            float n2 = fmaxf(sqrtf(Bv), 1e-12f);
            float intra = ((1.f - D1 / (n1 * cc1)) + (1.f - D2 / (n2 * cc2))) / (float)(NCLS - 1);
            float S11 = A  / (n1 * n1);
            float S22 = Bv / (n2 * n2);
            float S12 = C  / (n1 * n2);
            bool mk[NCLS][NCLS] = {};
            for (int r = 1; r < NCLS; r++) {
                for (int j = 0; j < 3; j++) {
                    int n = nb[(img * NCLS + r) * 3 + j];
                    if (n == 0) break;      // cumprod break semantics
                    mk[r][n] = true;        // scatter-max: duplicates count once
                }
            }
            float ssum = 0.f, msum = 0.f;
            for (int r = 1; r < NCLS; r++)
                for (int c = 0; c < NCLS; c++)
                    if (mk[r][c]) {
                        msum += 1.f;
                        float Sv = 0.f;
                        if (r == 1) Sv = (c == 1) ? S11 : ((c == 2) ? S12 : 0.f);
                        else        Sv = (c == 1) ? S12 : ((c == 2) ? S22 : 0.f);
                        ssum += Sv;
                    }
            part[img] = intra + ssum / msum + ceb * (1.0f / (float)HW);
        }
    }
    __syncthreads();
    if (tid == 0) {
        float tot = 0.f;
        #pragma unroll
        for (int i = 0; i < BATCH; i++) tot += part[i];
        out[0] = tot;
    }
}

extern "C" void kernel_launch(void* const* d_in, const int* in_sizes, int n_in,
                              void* d_out, int out_size) {
    const float* emb  = (const float*)d_in[0];
    const float* pred = (const float*)d_in[1];
    const int*   lab  = (const int*)d_in[2];
    const int*   nb   = (const int*)d_in[3];

    cudaFuncSetAttribute(main_kernel, cudaFuncAttributeMaxDynamicSharedMemorySize, SMEM_BYTES);

    main_kernel<<<dim3(GX, BATCH), 256, SMEM_BYTES>>>(emb, pred, lab, nb, (float*)d_out);
}

// round 4
// speedup vs baseline: 1.1425x; 1.1425x over previous
#include <cuda_runtime.h>

#define BATCH 16
#define ECH 32
#define NCLS 3
#define HW 262144           // 512*512
#define HW2 131072
#define TILE_PX 512
#define NTILES 512          // HW / TILE_PX
#define GX 18               // grid (18,16) = 288 blocks = 2 CTAs/SM on 144 SMs
#define NBLK (GX*BATCH)     // 288
#define ROWS 516            // stride mod 32 == 4 -> conflict-free LDS.128 in phase B

// shared memory layout (floats) — SINGLE buffer (register-prefetch pipelining)
#define OFF_VALS 0
#define OFF_META (ECH*ROWS)              // 16512
#define OFF_RED  (OFF_META + TILE_PX)    // 17024
#define OFF_SCR  (OFF_RED + 8*4*32)      // 18048
#define SM_FLOATS (OFF_SCR + 32)         // 18080
#define SMEM_BYTES (SM_FLOATS*4)         // 72320  -> 2 CTAs/SM (144.6 KB of 228)

// per-block partial results (unique slots -> no zeroing, no atomics on data)
__device__ float g_part[BATCH][GX][4][ECH]; // [0]=sum_emb_l1 [1]=sum_hat_l1 [2]=sum_emb_l2 [3]=sum_hat_l2
__device__ float g_misc[BATCH][GX][3];      // ce, c1, c2
__device__ unsigned int g_sync;             // zero-init; atomicInc wraps -> graph-replay safe

__global__ __launch_bounds__(256, 2)
void main_kernel(const float* __restrict__ emb,
                 const float* __restrict__ pred,
                 const int*  __restrict__ lab,
                 const int*  __restrict__ nb,
                 float* __restrict__ out) {
    extern __shared__ float sm[];
    float* vals  = sm + OFF_VALS;
    float* metaT = sm + OFF_META;

    const int b    = blockIdx.y;
    const int tid  = threadIdx.x;
    const int wid  = tid >> 5;
    const int lane = tid & 31;

    const float2* emb2 = (const float2*)emb + (size_t)b * ECH  * HW2;
    const float2* pr2  = (const float2*)pred + (size_t)b * NCLS * HW2;
    const int2*   lb2  = (const int2*)lab + (size_t)b * HW2;

    // accumulators (lane == channel in phase B)
    float a1 = 0.f, h1 = 0.f, a2 = 0.f, h2 = 0.f;
    float ce = 0.f;
    int   c1 = 0, c2 = 0;

    // prefetch registers
    float2 v[ECH];
    int2   lp;
    float2 q0, q1, q2;

    // ---------------- prologue: load tile blockIdx.x, consume into buffer ----------------
    {
        const int qp = blockIdx.x * (TILE_PX / 2) + tid;
        #pragma unroll
        for (int e = 0; e < ECH; e++) v[e] = emb2[e * HW2 + qp];
        lp = lb2[qp];
        q0 = pr2[qp]; q1 = pr2[HW2 + qp]; q2 = pr2[2 * HW2 + qp];

        float sx = 0.f, sy = 0.f;
        #pragma unroll
        for (int e = 0; e < ECH; e++) {
            float2 w = v[e];
            sx = fmaf(w.x, w.x, sx);
            sy = fmaf(w.y, w.y, sy);
            *(float2*)&vals[e * ROWS + 2 * tid] = w;
        }
        float rx = 1.f / fmaxf(sqrtf(sx), 1e-8f);
        float ry = 1.f / fmaxf(sqrtf(sy), 1e-8f);
        metaT[2 * tid]     = (lp.x == 1) ? rx : ((lp.x == 2) ? -rx : 0.f);
        metaT[2 * tid + 1] = (lp.y == 1) ? ry : ((lp.y == 2) ? -ry : 0.f);
        c1 += (lp.x == 1) + (lp.y == 1);
        c2 += (lp.x == 2) + (lp.y == 2);
        float m   = fmaxf(q0.x, fmaxf(q1.x, q2.x));
        ce += m + __logf(__expf(q0.x - m) + __expf(q1.x - m) + __expf(q2.x - m))
              - ((lp.x == 0) ? q0.x : ((lp.x == 1) ? q1.x : q2.x));
        m = fmaxf(q0.y, fmaxf(q1.y, q2.y));
        ce += m + __logf(__expf(q0.y - m) + __expf(q1.y - m) + __expf(q2.y - m))
              - ((lp.y == 0) ? q0.y : ((lp.y == 1) ? q1.y : q2.y));
    }
    __syncthreads();

    // ---------------- pipelined main loop (single buffer, reg prefetch) ----------------
    for (int i = 0; ; i++) {
        const int tn = blockIdx.x + (i + 1) * GX;
        const bool more = (tn < NTILES);

        // issue next tile's global loads (in flight across phase B + barrier)
        if (more) {
            const int qp = tn * (TILE_PX / 2) + tid;
            #pragma unroll
            for (int e = 0; e < ECH; e++) v[e] = emb2[e * HW2 + qp];
            lp = lb2[qp];
            q0 = pr2[qp]; q1 = pr2[HW2 + qp]; q2 = pr2[2 * HW2 + qp];
        }

        // phase B: warp = 32 channels, 64 px/warp, float4 smem loads
        {
            const float* vrow = vals  + lane * ROWS + wid * 64;
            const float* mrow = metaT + wid * 64;
            #pragma unroll 4
            for (int k = 0; k < 16; k++) {
                float4 w = *(const float4*)(vrow + 4 * k);
                float4 t = *(const float4*)(mrow + 4 * k);   // broadcast within warp
                float vh0 = w.x * fabsf(t.x);
                float vh1 = w.y * fabsf(t.y);
                float vh2 = w.z * fabsf(t.z);
                float vh3 = w.w * fabsf(t.w);
                if      (t.x > 0.f) { a1 += w.x; h1 += vh0; }
                else if (t.x < 0.f) { a2 += w.x; h2 += vh0; }
                if      (t.y > 0.f) { a1 += w.y; h1 += vh1; }
                else if (t.y < 0.f) { a2 += w.y; h2 += vh1; }
                if      (t.z > 0.f) { a1 += w.z; h1 += vh2; }
                else if (t.z < 0.f) { a2 += w.z; h2 += vh2; }
                if      (t.w > 0.f) { a1 += w.w; h1 += vh3; }
                else if (t.w < 0.f) { a2 += w.w; h2 += vh3; }
            }
        }
        if (!more) break;
        __syncthreads();   // phase B reads done before overwrite

        // consume prefetched regs into the (single) buffer
        {
            float sx = 0.f, sy = 0.f;
            #pragma unroll
            for (int e = 0; e < ECH; e++) {
                float2 w = v[e];
                sx = fmaf(w.x, w.x, sx);
                sy = fmaf(w.y, w.y, sy);
                *(float2*)&vals[e * ROWS + 2 * tid] = w;
            }
            float rx = 1.f / fmaxf(sqrtf(sx), 1e-8f);
            float ry = 1.f / fmaxf(sqrtf(sy), 1e-8f);
            metaT[2 * tid]     = (lp.x == 1) ? rx : ((lp.x == 2) ? -rx : 0.f);
            metaT[2 * tid + 1] = (lp.y == 1) ? ry : ((lp.y == 2) ? -ry : 0.f);
            c1 += (lp.x == 1) + (lp.y == 1);
            c2 += (lp.x == 2) + (lp.y == 2);
            float m   = fmaxf(q0.x, fmaxf(q1.x, q2.x));
            ce += m + __logf(__expf(q0.x - m) + __expf(q1.x - m) + __expf(q2.x - m))
                  - ((lp.x == 0) ? q0.x : ((lp.x == 1) ? q1.x : q2.x));
            m = fmaxf(q0.y, fmaxf(q1.y, q2.y));
            ce += m + __logf(__expf(q0.y - m) + __expf(q1.y - m) + __expf(q2.y - m))
                  - ((lp.y == 0) ? q0.y : ((lp.y == 1) ? q1.y : q2.y));
        }
        __syncthreads();   // writes visible before next phase B
    }

    // ---------------- block reduction -> unique global slots ----------------
    float* red = sm + OFF_RED;
    float* scr = sm + OFF_SCR;
    __syncthreads();
    red[(wid * 4 + 0) * 32 + lane] = a1;
    red[(wid * 4 + 1) * 32 + lane] = h1;
    red[(wid * 4 + 2) * 32 + lane] = a2;
    red[(wid * 4 + 3) * 32 + lane] = h2;
    float cef = ce; float c1f = (float)c1, c2f = (float)c2;
    #pragma unroll
    for (int o = 16; o; o >>= 1) {
        cef += __shfl_xor_sync(0xffffffffu, cef, o);
        c1f += __shfl_xor_sync(0xffffffffu, c1f, o);
        c2f += __shfl_xor_sync(0xffffffffu, c2f, o);
    }
    if (lane == 0) { scr[wid] = cef; scr[8 + wid] = c1f; scr[16 + wid] = c2f; }
    __syncthreads();

    if (wid < 4) {
        float s = 0.f;
        #pragma unroll
        for (int w = 0; w < 8; w++) s += red[(w * 4 + wid) * 32 + lane];
        g_part[b][blockIdx.x][wid][lane] = s;
    }
    if (tid == 0) {
        float tce = 0.f, t1 = 0.f, t2 = 0.f;
        for (int w = 0; w < 8; w++) { tce += scr[w]; t1 += scr[8 + w]; t2 += scr[16 + w]; }
        g_misc[b][blockIdx.x][0] = tce;
        g_misc[b][blockIdx.x][1] = t1;
        g_misc[b][blockIdx.x][2] = t2;
    }

    // ---------------- last-CTA fused finalize ----------------
    __threadfence();
    __syncthreads();
    __shared__ unsigned int s_last;
    if (tid == 0) s_last = atomicInc(&g_sync, NBLK - 1);  // wraps to 0 each launch
    __syncthreads();
    if (s_last != NBLK - 1) return;
    __threadfence();

    float* part = scr;   // 16 floats of scratch
    for (int img = wid; img < BATCH; img += 8) {
        float s1 = 0.f, hh1 = 0.f, s2 = 0.f, hh2 = 0.f;
        float ceb = 0.f, cc1 = 0.f, cc2 = 0.f;
        #pragma unroll
        for (int x = 0; x < GX; x++) {
            s1  += g_part[img][x][0][lane];
            hh1 += g_part[img][x][1][lane];
            s2  += g_part[img][x][2][lane];
            hh2 += g_part[img][x][3][lane];
            ceb += g_misc[img][x][0];
            cc1 += g_misc[img][x][1];
            cc2 += g_misc[img][x][2];
        }
        float m1 = s1 / cc1, m2 = s2 / cc2;
        float A  = m1 * m1;
        float Bv = m2 * m2;
        float C  = m1 * m2;
        float D1 = m1 * hh1;
        float D2 = m2 * hh2;
        #pragma unroll
        for (int o = 16; o; o >>= 1) {
            A  += __shfl_xor_sync(0xffffffffu, A,  o);
            Bv += __shfl_xor_sync(0xffffffffu, Bv, o);
            C  += __shfl_xor_sync(0xffffffffu, C,  o);
            D1 += __shfl_xor_sync(0xffffffffu, D1, o);
            D2 += __shfl_xor_sync(0xffffffffu, D2, o);
        }
        if (lane == 0) {
            float n1 = fmaxf(sqrtf(A),  1e-12f);
            float n2 = fmaxf(sqrtf(Bv), 1e-12f);
            float intra = ((1.f - D1 / (n1 * cc1)) + (1.f - D2 / (n2 * cc2))) / (float)(NCLS - 1);
            float S11 = A  / (n1 * n1);
            float S22 = Bv / (n2 * n2);
            float S12 = C  / (n1 * n2);
            bool mk[NCLS][NCLS] = {};
            for (int r = 1; r < NCLS; r++) {
                for (int j = 0; j < 3; j++) {
                    int n = nb[(img * NCLS + r) * 3 + j];
                    if (n == 0) break;      // cumprod break semantics
                    mk[r][n] = true;        // scatter-max: duplicates count once
                }
            }
            float ssum = 0.f, msum = 0.f;
            for (int r = 1; r < NCLS; r++)
                for (int c = 0; c < NCLS; c++)
                    if (mk[r][c]) {
                        msum += 1.f;
                        float Sv = 0.f;
                        if (r == 1) Sv = (c == 1) ? S11 : ((c == 2) ? S12 : 0.f);
                        else        Sv = (c == 1) ? S12 : ((c == 2) ? S22 : 0.f);
                        ssum += Sv;
                    }
            part[img] = intra + ssum / msum + ceb * (1.0f / (float)HW);
        }
    }
    __syncthreads();
    if (tid == 0) {
        float tot = 0.f;
        #pragma unroll
        for (int i = 0; i < BATCH; i++) tot += part[i];
        out[0] = tot;
    }
}

extern "C" void kernel_launch(void* const* d_in, const int* in_sizes, int n_in,
                              void* d_out, int out_size) {
    const float* emb  = (const float*)d_in[0];
    const float* pred = (const float*)d_in[1];
    const int*   lab  = (const int*)d_in[2];
    const int*   nb   = (const int*)d_in[3];

    cudaFuncSetAttribute(main_kernel, cudaFuncAttributeMaxDynamicSharedMemorySize, SMEM_BYTES);

    main_kernel<<<dim3(GX, BATCH), 256, SMEM_BYTES>>>(emb, pred, lab, nb, (float*)d_out);
}

// round 5
// speedup vs baseline: 1.1905x; 1.0420x over previous
#include <cuda_runtime.h>

#define BATCH 16
#define ECH 32
#define NCLS 3
#define HW 262144           // 512*512
#define HW2 131072
#define WCHUNK 64           // pixels per warp-chunk
#define NCHUNK (HW/WCHUNK)  // 4096 chunks per image
#define GX 18               // grid (18,16) = 288 blocks = 2 CTAs/SM on 144 SMs
#define NBLK (GX*BATCH)     // 288
#define NWSLOT (GX*8)       // 144 warp-slots per image
#define WROWS 68            // per-warp row stride (mod 32 == 4 -> conflict-free LDS.128)

// shared memory layout (floats): 8 warp-private regions, then meta/red/scr
#define WREG (ECH*WROWS)               // 2176 floats per warp region
#define OFF_META (8*WREG)              // 17408
#define OFF_RED  (OFF_META + 8*64)     // 17920
#define OFF_SCR  (OFF_RED + 8*4*32)    // 18944
#define SM_FLOATS (OFF_SCR + 32)       // 18976
#define SMEM_BYTES (SM_FLOATS*4)       // 75904 -> 2 CTAs/SM (148 KB of 228)

// per-block partial results (unique slots -> no zeroing, no atomics on data)
__device__ float g_part[BATCH][GX][4][ECH]; // [0]=sum_emb_l1 [1]=sum_hat_l1 [2]=sum_emb_l2 [3]=sum_hat_l2
__device__ float g_misc[BATCH][GX][3];      // ce, c1, c2
__device__ unsigned int g_sync;             // zero-init; atomicInc wraps -> graph-replay safe

__global__ __launch_bounds__(256, 2)
void main_kernel(const float* __restrict__ emb,
                 const float* __restrict__ pred,
                 const int*  __restrict__ lab,
                 const int*  __restrict__ nb,
                 float* __restrict__ out) {
    extern __shared__ float sm[];

    const int b    = blockIdx.y;
    const int tid  = threadIdx.x;
    const int wid  = tid >> 5;
    const int lane = tid & 31;
    const int gw   = blockIdx.x * 8 + wid;     // global warp-slot in [0,144)

    float* valsW = sm + wid * WREG;            // [ECH][WROWS] warp-private
    float* metaW = sm + OFF_META + wid * 64;   // [64] warp-private

    const float2* emb2 = (const float2*)emb + (size_t)b * ECH  * HW2;
    const float2* pr2  = (const float2*)pred + (size_t)b * NCLS * HW2;
    const int2*   lb2  = (const int2*)lab + (size_t)b * HW2;

    // accumulators (lane == channel in phase B)
    float a1 = 0.f, h1 = 0.f, a2 = 0.f, h2 = 0.f;
    float ce = 0.f;
    int   c1 = 0, c2 = 0;

    // prefetch registers
    float2 v[ECH];
    int2   lp;
    float2 q0, q1, q2;

    // ---------------- prologue: load chunk gw, consume into warp buffer ----------------
    {
        const int qp = gw * 32 + lane;          // float2 (pixel-pair) index
        #pragma unroll
        for (int e = 0; e < ECH; e++) v[e] = emb2[e * HW2 + qp];
        lp = lb2[qp];
        q0 = pr2[qp]; q1 = pr2[HW2 + qp]; q2 = pr2[2 * HW2 + qp];

        float sx = 0.f, sy = 0.f;
        #pragma unroll
        for (int e = 0; e < ECH; e++) {
            float2 w = v[e];
            sx = fmaf(w.x, w.x, sx);
            sy = fmaf(w.y, w.y, sy);
            *(float2*)&valsW[e * WROWS + 2 * lane] = w;
        }
        float rx = 1.f / fmaxf(sqrtf(sx), 1e-8f);
        float ry = 1.f / fmaxf(sqrtf(sy), 1e-8f);
        *(float2*)&metaW[2 * lane] = make_float2(
            (lp.x == 1) ? rx : ((lp.x == 2) ? -rx : 0.f),
            (lp.y == 1) ? ry : ((lp.y == 2) ? -ry : 0.f));
        c1 += (lp.x == 1) + (lp.y == 1);
        c2 += (lp.x == 2) + (lp.y == 2);
        float m   = fmaxf(q0.x, fmaxf(q1.x, q2.x));
        ce += m + __logf(__expf(q0.x - m) + __expf(q1.x - m) + __expf(q2.x - m))
              - ((lp.x == 0) ? q0.x : ((lp.x == 1) ? q1.x : q2.x));
        m = fmaxf(q0.y, fmaxf(q1.y, q2.y));
        ce += m + __logf(__expf(q0.y - m) + __expf(q1.y - m) + __expf(q2.y - m))
              - ((lp.y == 0) ? q0.y : ((lp.y == 1) ? q1.y : q2.y));
    }
    __syncwarp();

    // ---------------- warp-autonomous pipelined loop (NO block barriers) ----------------
    for (int i = 0; ; i++) {
        const int nidx = gw + (i + 1) * NWSLOT;
        const bool more = (nidx < NCHUNK);

        // issue next chunk's global loads (in flight across phase B)
        if (more) {
            const int qp = nidx * 32 + lane;
            #pragma unroll
            for (int e = 0; e < ECH; e++) v[e] = emb2[e * HW2 + qp];
            lp = lb2[qp];
            q0 = pr2[qp]; q1 = pr2[HW2 + qp]; q2 = pr2[2 * HW2 + qp];
        }

        // phase B: lane = channel, 64 px via 16 float4 reads (conflict-free, WROWS%32==4)
        {
            const float* vrow = valsW + lane * WROWS;
            #pragma unroll 4
            for (int k = 0; k < 16; k++) {
                float4 w = *(const float4*)(vrow + 4 * k);
                float4 t = *(const float4*)(metaW + 4 * k);   // broadcast within warp
                float vh0 = w.x * fabsf(t.x);
                float vh1 = w.y * fabsf(t.y);
                float vh2 = w.z * fabsf(t.z);
                float vh3 = w.w * fabsf(t.w);
                if      (t.x > 0.f) { a1 += w.x; h1 += vh0; }
                else if (t.x < 0.f) { a2 += w.x; h2 += vh0; }
                if      (t.y > 0.f) { a1 += w.y; h1 += vh1; }
                else if (t.y < 0.f) { a2 += w.y; h2 += vh1; }
                if      (t.z > 0.f) { a1 += w.z; h1 += vh2; }
                else if (t.z < 0.f) { a2 += w.z; h2 += vh2; }
                if      (t.w > 0.f) { a1 += w.w; h1 += vh3; }
                else if (t.w < 0.f) { a2 += w.w; h2 += vh3; }
            }
        }
        if (!more) break;
        __syncwarp();   // phase B reads done before overwrite

        // consume prefetched regs into own buffer
        {
            float sx = 0.f, sy = 0.f;
            #pragma unroll
            for (int e = 0; e < ECH; e++) {
                float2 w = v[e];
                sx = fmaf(w.x, w.x, sx);
                sy = fmaf(w.y, w.y, sy);
                *(float2*)&valsW[e * WROWS + 2 * lane] = w;
            }
            float rx = 1.f / fmaxf(sqrtf(sx), 1e-8f);
            float ry = 1.f / fmaxf(sqrtf(sy), 1e-8f);
            *(float2*)&metaW[2 * lane] = make_float2(
                (lp.x == 1) ? rx : ((lp.x == 2) ? -rx : 0.f),
                (lp.y == 1) ? ry : ((lp.y == 2) ? -ry : 0.f));
            c1 += (lp.x == 1) + (lp.y == 1);
            c2 += (lp.x == 2) + (lp.y == 2);
            float m   = fmaxf(q0.x, fmaxf(q1.x, q2.x));
            ce += m + __logf(__expf(q0.x - m) + __expf(q1.x - m) + __expf(q2.x - m))
                  - ((lp.x == 0) ? q0.x : ((lp.x == 1) ? q1.x : q2.x));
            m = fmaxf(q0.y, fmaxf(q1.y, q2.y));
            ce += m + __logf(__expf(q0.y - m) + __expf(q1.y - m) + __expf(q2.y - m))
                  - ((lp.y == 0) ? q0.y : ((lp.y == 1) ? q1.y : q2.y));
        }
        __syncwarp();   // writes visible before next phase B
    }

    // ---------------- block reduction -> unique global slots ----------------
    float* red = sm + OFF_RED;
    float* scr = sm + OFF_SCR;
    // each warp writes its own red slice (disjoint from vals regions) — no barrier needed yet
    red[(wid * 4 + 0) * 32 + lane] = a1;
    red[(wid * 4 + 1) * 32 + lane] = h1;
    red[(wid * 4 + 2) * 32 + lane] = a2;
    red[(wid * 4 + 3) * 32 + lane] = h2;
    float cef = ce; float c1f = (float)c1, c2f = (float)c2;
    #pragma unroll
    for (int o = 16; o; o >>= 1) {
        cef += __shfl_xor_sync(0xffffffffu, cef, o);
        c1f += __shfl_xor_sync(0xffffffffu, c1f, o);
        c2f += __shfl_xor_sync(0xffffffffu, c2f, o);
    }
    if (lane == 0) { scr[wid] = cef; scr[8 + wid] = c1f; scr[16 + wid] = c2f; }
    __syncthreads();

    if (wid < 4) {
        float s = 0.f;
        #pragma unroll
        for (int w = 0; w < 8; w++) s += red[(w * 4 + wid) * 32 + lane];
        g_part[b][blockIdx.x][wid][lane] = s;
    }
    if (tid == 0) {
        float tce = 0.f, t1 = 0.f, t2 = 0.f;
        for (int w = 0; w < 8; w++) { tce += scr[w]; t1 += scr[8 + w]; t2 += scr[16 + w]; }
        g_misc[b][blockIdx.x][0] = tce;
        g_misc[b][blockIdx.x][1] = t1;
        g_misc[b][blockIdx.x][2] = t2;
    }

    // ---------------- last-CTA fused finalize ----------------
    __threadfence();
    __syncthreads();
    __shared__ unsigned int s_last;
    if (tid == 0) s_last = atomicInc(&g_sync, NBLK - 1);  // wraps to 0 each launch
    __syncthreads();
    if (s_last != NBLK - 1) return;
    __threadfence();

    float* part = scr;   // 16 floats of scratch
    for (int img = wid; img < BATCH; img += 8) {
        float s1 = 0.f, hh1 = 0.f, s2 = 0.f, hh2 = 0.f;
        float ceb = 0.f, cc1 = 0.f, cc2 = 0.f;
        #pragma unroll
        for (int x = 0; x < GX; x++) {
            s1  += g_part[img][x][0][lane];
            hh1 += g_part[img][x][1][lane];
            s2  += g_part[img][x][2][lane];
            hh2 += g_part[img][x][3][lane];
            ceb += g_misc[img][x][0];
            cc1 += g_misc[img][x][1];
            cc2 += g_misc[img][x][2];
        }
        float m1 = s1 / cc1, m2 = s2 / cc2;
        float A  = m1 * m1;
        float Bv = m2 * m2;
        float C  = m1 * m2;
        float D1 = m1 * hh1;
        float D2 = m2 * hh2;
        #pragma unroll
        for (int o = 16; o; o >>= 1) {
            A  += __shfl_xor_sync(0xffffffffu, A,  o);
            Bv += __shfl_xor_sync(0xffffffffu, Bv, o);
            C  += __shfl_xor_sync(0xffffffffu, C,  o);
            D1 += __shfl_xor_sync(0xffffffffu, D1, o);
            D2 += __shfl_xor_sync(0xffffffffu, D2, o);
        }
        if (lane == 0) {
            float n1 = fmaxf(sqrtf(A),  1e-12f);
            float n2 = fmaxf(sqrtf(Bv), 1e-12f);
            float intra = ((1.f - D1 / (n1 * cc1)) + (1.f - D2 / (n2 * cc2))) / (float)(NCLS - 1);
            float S11 = A  / (n1 * n1);
            float S22 = Bv / (n2 * n2);
            float S12 = C  / (n1 * n2);
            bool mk[NCLS][NCLS] = {};
            for (int r = 1; r < NCLS; r++) {
                for (int j = 0; j < 3; j++) {
                    int n = nb[(img * NCLS + r) * 3 + j];
                    if (n == 0) break;      // cumprod break semantics
                    mk[r][n] = true;        // scatter-max: duplicates count once
                }
            }
            float ssum = 0.f, msum = 0.f;
            for (int r = 1; r < NCLS; r++)
                for (int c = 0; c < NCLS; c++)
                    if (mk[r][c]) {
                        msum += 1.f;
                        float Sv = 0.f;
                        if (r == 1) Sv = (c == 1) ? S11 : ((c == 2) ? S12 : 0.f);
                        else        Sv = (c == 1) ? S12 : ((c == 2) ? S22 : 0.f);
                        ssum += Sv;
                    }
            part[img] = intra + ssum / msum + ceb * (1.0f / (float)HW);
        }
    }
    __syncthreads();
    if (tid == 0) {
        float tot = 0.f;
        #pragma unroll
        for (int i = 0; i < BATCH; i++) tot += part[i];
        out[0] = tot;
    }
}

extern "C" void kernel_launch(void* const* d_in, const int* in_sizes, int n_in,
                              void* d_out, int out_size) {
    const float* emb  = (const float*)d_in[0];
    const float* pred = (const float*)d_in[1];
    const int*   lab  = (const int*)d_in[2];
    const int*   nb   = (const int*)d_in[3];

    cudaFuncSetAttribute(main_kernel, cudaFuncAttributeMaxDynamicSharedMemorySize, SMEM_BYTES);

    main_kernel<<<dim3(GX, BATCH), 256, SMEM_BYTES>>>(emb, pred, lab, nb, (float*)d_out);
}